// round 1
// baseline (speedup 1.0000x reference)
#include <cuda_runtime.h>
#include <cstdint>

#define IN_FEAT  64
#define OUT_FEAT 64
#define MAX_NODES 100000

// Scratch for h = feat @ W + b  (25.6 MB). __device__ global: allocation-free.
__device__ float g_h[MAX_NODES * OUT_FEAT];

// ---------------------------------------------------------------------------
// Kernel 1: h = feat @ W + b
// 256 threads/block -> 4 rows per block, 64 threads per row (one per out col).
// W (64x64 fp32 = 16KB) staged in shared; feat row reads are warp-broadcast.
// ---------------------------------------------------------------------------
__global__ __launch_bounds__(256) void gemm_kernel(
    const float* __restrict__ feat,
    const float* __restrict__ W,
    const float* __restrict__ bias,
    float* __restrict__ h,
    int n_nodes)
{
    __shared__ float sW[IN_FEAT * OUT_FEAT];
    for (int i = threadIdx.x; i < IN_FEAT * OUT_FEAT; i += blockDim.x)
        sW[i] = W[i];
    __syncthreads();

    int j         = threadIdx.x & 63;        // output column
    int local_row = threadIdx.x >> 6;        // 0..3
    int row       = blockIdx.x * 4 + local_row;
    if (row >= n_nodes) return;

    const float* frow = feat + (size_t)row * IN_FEAT;
    float acc = bias[j];
#pragma unroll
    for (int k = 0; k < IN_FEAT; k++)
        acc = fmaf(__ldg(frow + k), sW[k * OUT_FEAT + j], acc);

    h[(size_t)row * OUT_FEAT + j] = acc;
}

// ---------------------------------------------------------------------------
// Kernel 2: zero the output (harness poisons d_out to 0xAA)
// ---------------------------------------------------------------------------
__global__ void zero_kernel(float4* __restrict__ out, int n4)
{
    int i = blockIdx.x * blockDim.x + threadIdx.x;
    if (i < n4) out[i] = make_float4(0.f, 0.f, 0.f, 0.f);
}

// ---------------------------------------------------------------------------
// Kernel 3: edge scatter.
// 16 threads per edge; each thread handles 4 floats:
//   v = h[src[e]][q*4 .. q*4+3] * att[e];  red.global.add.v4.f32 into out[dst[e]].
// red.* has no return path -> best atomic throughput on sm_103a.
// ---------------------------------------------------------------------------
__global__ __launch_bounds__(256) void scatter_kernel(
    const float* __restrict__ h,
    const float* __restrict__ att,
    const int*   __restrict__ src,
    const int*   __restrict__ dst,
    float* __restrict__ out,
    int n_edges)
{
    int idx = blockIdx.x * blockDim.x + threadIdx.x;
    int e = idx >> 4;        // edge
    int q = idx & 15;        // quarter-row chunk (4 floats)
    if (e >= n_edges) return;

    int   s = __ldg(src + e);        // broadcast within the 16-thread group
    int   d = __ldg(dst + e);
    float a = __ldg(att + e);

    float4 v = *reinterpret_cast<const float4*>(h + (size_t)s * OUT_FEAT + q * 4);
    v.x *= a; v.y *= a; v.z *= a; v.w *= a;

    float* o = out + (size_t)d * OUT_FEAT + q * 4;
    asm volatile("red.global.add.v4.f32 [%0], {%1, %2, %3, %4};"
                 :: "l"(o), "f"(v.x), "f"(v.y), "f"(v.z), "f"(v.w)
                 : "memory");
}

// ---------------------------------------------------------------------------
// Launch
// Inputs (metadata order): feat[N*64] f32, attention[E] f32, src[E] i32,
//                          dst[E] i32, weight[64*64] f32, h_bias[64] f32
// Output: out[N*64] f32
// ---------------------------------------------------------------------------
extern "C" void kernel_launch(void* const* d_in, const int* in_sizes, int n_in,
                              void* d_out, int out_size)
{
    const float* feat = (const float*)d_in[0];
    const float* att  = (const float*)d_in[1];
    const int*   src  = (const int*)  d_in[2];
    const int*   dst  = (const int*)  d_in[3];
    const float* W    = (const float*)d_in[4];
    const float* bias = (const float*)d_in[5];
    float*       out  = (float*)d_out;

    int n_nodes = in_sizes[0] / IN_FEAT;
    int n_edges = in_sizes[2];

    float* h;
    cudaGetSymbolAddress((void**)&h, g_h);

    // 1) h = feat @ W + b
    int gemm_blocks = (n_nodes + 3) / 4;
    gemm_kernel<<<gemm_blocks, 256>>>(feat, W, bias, h, n_nodes);

    // 2) zero output
    int n4 = out_size / 4;
    zero_kernel<<<(n4 + 255) / 256, 256>>>((float4*)d_out, n4);

    // 3) scatter edges
    long long work = (long long)n_edges * 16;
    int sblocks = (int)((work + 255) / 256);
    scatter_kernel<<<sblocks, 256>>>(h, att, src, dst, out, n_edges);
}

// round 2
// speedup vs baseline: 1.7657x; 1.7657x over previous
#include <cuda_runtime.h>
#include <cstdint>

#define IN_FEAT  64
#define OUT_FEAT 64
#define MAX_NODES 100000

// Scratch for h = feat @ W + b  (25.6 MB). __device__ global: allocation-free.
__device__ float g_h[MAX_NODES * OUT_FEAT];

// ---------------------------------------------------------------------------
// Kernel 1: h = feat @ W + b  — register-tiled SMEM GEMM.
// Block = 256 threads, output tile 64 rows x 64 cols, 4x4 micro-tile/thread.
// feat tile stored TRANSPOSED in smem (sF[k][row]) so both fragments are
// LDS.128 with intra-warp broadcast. Pad 68 kills bank conflicts, keeps
// 16B alignment (68*4 = 272 = 16*17).
// ---------------------------------------------------------------------------
__global__ __launch_bounds__(256) void gemm_kernel(
    const float* __restrict__ feat,
    const float* __restrict__ W,
    const float* __restrict__ bias,
    float* __restrict__ h,
    int n_nodes)
{
    __shared__ float sF[IN_FEAT][68];   // [k][local_row]
    __shared__ float sW[IN_FEAT][68];   // [k][col]

    const int tid  = threadIdx.x;
    const int row0 = blockIdx.x * 64;

    // ---- stage W[k][j] into sW (coalesced LDG.128) ----
    {
        int k  = tid >> 2;          // 0..63
        int c4 = tid & 3;           // 16-float chunk
        const float4* wsrc = reinterpret_cast<const float4*>(W + k * OUT_FEAT + c4 * 16);
#pragma unroll
        for (int i = 0; i < 4; i++) {
            float4 v = wsrc[i];
            int c = c4 * 16 + i * 4;
            sW[k][c + 0] = v.x; sW[k][c + 1] = v.y;
            sW[k][c + 2] = v.z; sW[k][c + 3] = v.w;
        }
    }
    // ---- stage feat tile transposed into sF[k][row] ----
    {
        int rl = tid >> 2;          // local row 0..63
        int c4 = tid & 3;
        int grow = row0 + rl;
        const float* frow = feat + (size_t)grow * IN_FEAT;
#pragma unroll
        for (int i = 0; i < 4; i++) {
            int k = c4 * 16 + i * 4;
            float4 v = (grow < n_nodes)
                ? *reinterpret_cast<const float4*>(frow + k)
                : make_float4(0.f, 0.f, 0.f, 0.f);
            sF[k + 0][rl] = v.x; sF[k + 1][rl] = v.y;
            sF[k + 2][rl] = v.z; sF[k + 3][rl] = v.w;
        }
    }
    __syncthreads();

    const int tx = tid & 15;   // col group (4 cols)
    const int ty = tid >> 4;   // row group (4 rows)

    float acc[4][4];
#pragma unroll
    for (int j = 0; j < 4; j++) {
        float b = __ldg(bias + tx * 4 + j);
#pragma unroll
        for (int i = 0; i < 4; i++) acc[i][j] = b;
    }

#pragma unroll 8
    for (int k = 0; k < IN_FEAT; k++) {
        float4 a = *reinterpret_cast<const float4*>(&sF[k][ty * 4]);
        float4 b = *reinterpret_cast<const float4*>(&sW[k][tx * 4]);
        float af[4] = {a.x, a.y, a.z, a.w};
        float bf[4] = {b.x, b.y, b.z, b.w};
#pragma unroll
        for (int i = 0; i < 4; i++)
#pragma unroll
            for (int j = 0; j < 4; j++)
                acc[i][j] = fmaf(af[i], bf[j], acc[i][j]);
    }

#pragma unroll
    for (int i = 0; i < 4; i++) {
        int grow = row0 + ty * 4 + i;
        if (grow < n_nodes) {
            float4 v = make_float4(acc[i][0], acc[i][1], acc[i][2], acc[i][3]);
            *reinterpret_cast<float4*>(h + (size_t)grow * OUT_FEAT + tx * 4) = v;
        }
    }
}

// ---------------------------------------------------------------------------
// Kernel 2: zero the output (harness poisons d_out to 0xAA)
// ---------------------------------------------------------------------------
__global__ void zero_kernel(float4* __restrict__ out, int n4)
{
    int i = blockIdx.x * blockDim.x + threadIdx.x;
    if (i < n4) out[i] = make_float4(0.f, 0.f, 0.f, 0.f);
}

// ---------------------------------------------------------------------------
// Kernel 3: edge scatter.
// 16 threads per edge; each thread handles 4 floats:
//   v = h[src[e]][q*4 .. q*4+3] * att[e];  red.global.add.v4.f32 into out[dst[e]].
// ---------------------------------------------------------------------------
__global__ __launch_bounds__(256) void scatter_kernel(
    const float* __restrict__ h,
    const float* __restrict__ att,
    const int*   __restrict__ src,
    const int*   __restrict__ dst,
    float* __restrict__ out,
    int n_edges)
{
    int idx = blockIdx.x * blockDim.x + threadIdx.x;
    int e = idx >> 4;        // edge
    int q = idx & 15;        // 4-float chunk
    if (e >= n_edges) return;

    int   s = __ldg(src + e);
    int   d = __ldg(dst + e);
    float a = __ldg(att + e);

    float4 v = *reinterpret_cast<const float4*>(h + (size_t)s * OUT_FEAT + q * 4);
    v.x *= a; v.y *= a; v.z *= a; v.w *= a;

    float* o = out + (size_t)d * OUT_FEAT + q * 4;
    asm volatile("red.global.add.v4.f32 [%0], {%1, %2, %3, %4};"
                 :: "l"(o), "f"(v.x), "f"(v.y), "f"(v.z), "f"(v.w)
                 : "memory");
}

// ---------------------------------------------------------------------------
// Launch
// ---------------------------------------------------------------------------
extern "C" void kernel_launch(void* const* d_in, const int* in_sizes, int n_in,
                              void* d_out, int out_size)
{
    const float* feat = (const float*)d_in[0];
    const float* att  = (const float*)d_in[1];
    const int*   src  = (const int*)  d_in[2];
    const int*   dst  = (const int*)  d_in[3];
    const float* W    = (const float*)d_in[4];
    const float* bias = (const float*)d_in[5];
    float*       out  = (float*)d_out;

    int n_nodes = in_sizes[0] / IN_FEAT;
    int n_edges = in_sizes[2];

    float* h;
    cudaGetSymbolAddress((void**)&h, g_h);

    // 1) h = feat @ W + b
    int gemm_blocks = (n_nodes + 63) / 64;
    gemm_kernel<<<gemm_blocks, 256>>>(feat, W, bias, h, n_nodes);

    // 2) zero output
    int n4 = out_size / 4;
    zero_kernel<<<(n4 + 255) / 256, 256>>>((float4*)d_out, n4);

    // 3) scatter edges
    long long work = (long long)n_edges * 16;
    int sblocks = (int)((work + 255) / 256);
    scatter_kernel<<<sblocks, 256>>>(h, att, src, dst, out, n_edges);
}

// round 3
// speedup vs baseline: 2.0080x; 1.1372x over previous
#include <cuda_runtime.h>
#include <cstdint>

#define IN_FEAT   64
#define OUT_FEAT  64
#define MAX_NODES 100000
#define MAX_EDGES 1600000
#define NB_SCAN   ((MAX_NODES + 255) / 256)   // 391

// Scratch (__device__ globals: allocation-free)
__device__ float g_h[MAX_NODES * OUT_FEAT];       // h = feat@W + b (25.6 MB)
__device__ int   g_cnt[MAX_NODES];                // histogram
__device__ int   g_off[MAX_NODES + 1];            // CSR offsets (exclusive scan)
__device__ int   g_cur[MAX_NODES];                // scatter cursors
__device__ int   g_bsum[NB_SCAN];                 // scan block sums
__device__ int2  g_pair[MAX_EDGES];               // dst-sorted (src, att) pairs

// ---------------------------------------------------------------------------
// Kernel 1: h = feat @ W + b — register-tiled SMEM GEMM (unchanged from R2)
// ---------------------------------------------------------------------------
__global__ __launch_bounds__(256) void gemm_kernel(
    const float* __restrict__ feat,
    const float* __restrict__ W,
    const float* __restrict__ bias,
    float* __restrict__ h,
    int n_nodes)
{
    __shared__ float sF[IN_FEAT][68];
    __shared__ float sW[IN_FEAT][68];

    const int tid  = threadIdx.x;
    const int row0 = blockIdx.x * 64;

    {
        int k  = tid >> 2;
        int c4 = tid & 3;
        const float4* wsrc = reinterpret_cast<const float4*>(W + k * OUT_FEAT + c4 * 16);
#pragma unroll
        for (int i = 0; i < 4; i++) {
            float4 v = wsrc[i];
            int c = c4 * 16 + i * 4;
            sW[k][c + 0] = v.x; sW[k][c + 1] = v.y;
            sW[k][c + 2] = v.z; sW[k][c + 3] = v.w;
        }
    }
    {
        int rl = tid >> 2;
        int c4 = tid & 3;
        int grow = row0 + rl;
        const float* frow = feat + (size_t)grow * IN_FEAT;
#pragma unroll
        for (int i = 0; i < 4; i++) {
            int k = c4 * 16 + i * 4;
            float4 v = (grow < n_nodes)
                ? *reinterpret_cast<const float4*>(frow + k)
                : make_float4(0.f, 0.f, 0.f, 0.f);
            sF[k + 0][rl] = v.x; sF[k + 1][rl] = v.y;
            sF[k + 2][rl] = v.z; sF[k + 3][rl] = v.w;
        }
    }
    __syncthreads();

    const int tx = tid & 15;
    const int ty = tid >> 4;

    float acc[4][4];
#pragma unroll
    for (int j = 0; j < 4; j++) {
        float b = __ldg(bias + tx * 4 + j);
#pragma unroll
        for (int i = 0; i < 4; i++) acc[i][j] = b;
    }

#pragma unroll 8
    for (int k = 0; k < IN_FEAT; k++) {
        float4 a = *reinterpret_cast<const float4*>(&sF[k][ty * 4]);
        float4 b = *reinterpret_cast<const float4*>(&sW[k][tx * 4]);
        float af[4] = {a.x, a.y, a.z, a.w};
        float bf[4] = {b.x, b.y, b.z, b.w};
#pragma unroll
        for (int i = 0; i < 4; i++)
#pragma unroll
            for (int j = 0; j < 4; j++)
                acc[i][j] = fmaf(af[i], bf[j], acc[i][j]);
    }

#pragma unroll
    for (int i = 0; i < 4; i++) {
        int grow = row0 + ty * 4 + i;
        if (grow < n_nodes) {
            float4 v = make_float4(acc[i][0], acc[i][1], acc[i][2], acc[i][3]);
            *reinterpret_cast<float4*>(h + (size_t)grow * OUT_FEAT + tx * 4) = v;
        }
    }
}

// ---------------------------------------------------------------------------
// Binning: counting sort of edges by dst
// ---------------------------------------------------------------------------
__global__ void zero_cnt_kernel(int n)
{
    int i = blockIdx.x * blockDim.x + threadIdx.x;
    if (i < n) g_cnt[i] = 0;
}

__global__ void hist_kernel(const int* __restrict__ dst, int n_edges)
{
    int e = blockIdx.x * blockDim.x + threadIdx.x;
    if (e < n_edges) atomicAdd(&g_cnt[dst[e]], 1);
}

// scan1: per-block inclusive scan of g_cnt -> g_off (block-local), block totals
__global__ __launch_bounds__(256) void scan1_kernel(int n)
{
    __shared__ int s[256];
    int i = blockIdx.x * 256 + threadIdx.x;
    int v = (i < n) ? g_cnt[i] : 0;
    s[threadIdx.x] = v;
    __syncthreads();
#pragma unroll
    for (int off = 1; off < 256; off <<= 1) {
        int t = (threadIdx.x >= off) ? s[threadIdx.x - off] : 0;
        __syncthreads();
        s[threadIdx.x] += t;
        __syncthreads();
    }
    if (i < n) g_off[i] = s[threadIdx.x];
    if (threadIdx.x == 255) g_bsum[blockIdx.x] = s[255];
}

// scan2: single-block exclusive scan of block sums
__global__ __launch_bounds__(512) void scan2_kernel()
{
    __shared__ int s[512];
    int t = threadIdx.x;
    s[t] = (t < NB_SCAN) ? g_bsum[t] : 0;
    __syncthreads();
#pragma unroll
    for (int off = 1; off < 512; off <<= 1) {
        int v = (t >= off) ? s[t - off] : 0;
        __syncthreads();
        s[t] += v;
        __syncthreads();
    }
    if (t < NB_SCAN) g_bsum[t] = (t > 0) ? s[t - 1] : 0;
}

// scan3: global exclusive offsets + cursors
__global__ __launch_bounds__(256) void scan3_kernel(int n, int n_edges)
{
    int i = blockIdx.x * 256 + threadIdx.x;
    if (i < n) {
        int excl = g_off[i] - g_cnt[i] + g_bsum[blockIdx.x];
        g_off[i] = excl;
        g_cur[i] = excl;
    }
    if (i == 0) g_off[n] = n_edges;
}

// perm: place packed (src, att) pairs in dst-sorted order
__global__ void perm_kernel(const int* __restrict__ src,
                            const int* __restrict__ dst,
                            const float* __restrict__ att,
                            int n_edges)
{
    int e = blockIdx.x * blockDim.x + threadIdx.x;
    if (e >= n_edges) return;
    int d = dst[e];
    int p = atomicAdd(&g_cur[d], 1);
    g_pair[p] = make_int2(src[e], __float_as_int(att[e]));
}

// ---------------------------------------------------------------------------
// Accumulate: one warp per dst node, lane owns 2 feature columns.
// Atomic-free; writes every node (zeros for degree-0), so no zero pass.
// ---------------------------------------------------------------------------
__global__ __launch_bounds__(256) void accum_kernel(
    const float* __restrict__ h,
    float* __restrict__ out,
    int n_nodes)
{
    int warp = (blockIdx.x * 256 + threadIdx.x) >> 5;
    int lane = threadIdx.x & 31;
    if (warp >= n_nodes) return;

    int j   = g_off[warp];
    int end = g_off[warp + 1];

    float2 acc = make_float2(0.f, 0.f);

    // unroll x2 for memory-level parallelism
    for (; j + 1 < end; j += 2) {
        int2 p0 = __ldg(&g_pair[j]);
        int2 p1 = __ldg(&g_pair[j + 1]);
        float a0 = __int_as_float(p0.y);
        float a1 = __int_as_float(p1.y);
        float2 v0 = *reinterpret_cast<const float2*>(h + (size_t)p0.x * OUT_FEAT + lane * 2);
        float2 v1 = *reinterpret_cast<const float2*>(h + (size_t)p1.x * OUT_FEAT + lane * 2);
        acc.x = fmaf(a0, v0.x, acc.x);
        acc.y = fmaf(a0, v0.y, acc.y);
        acc.x = fmaf(a1, v1.x, acc.x);
        acc.y = fmaf(a1, v1.y, acc.y);
    }
    if (j < end) {
        int2 p = __ldg(&g_pair[j]);
        float a = __int_as_float(p.y);
        float2 v = *reinterpret_cast<const float2*>(h + (size_t)p.x * OUT_FEAT + lane * 2);
        acc.x = fmaf(a, v.x, acc.x);
        acc.y = fmaf(a, v.y, acc.y);
    }

    *reinterpret_cast<float2*>(out + (size_t)warp * OUT_FEAT + lane * 2) = acc;
}

// ---------------------------------------------------------------------------
// Launch
// ---------------------------------------------------------------------------
extern "C" void kernel_launch(void* const* d_in, const int* in_sizes, int n_in,
                              void* d_out, int out_size)
{
    const float* feat = (const float*)d_in[0];
    const float* att  = (const float*)d_in[1];
    const int*   src  = (const int*)  d_in[2];
    const int*   dst  = (const int*)  d_in[3];
    const float* W    = (const float*)d_in[4];
    const float* bias = (const float*)d_in[5];
    float*       out  = (float*)d_out;

    int n_nodes = in_sizes[0] / IN_FEAT;
    int n_edges = in_sizes[2];

    float* h;
    cudaGetSymbolAddress((void**)&h, g_h);

    // 1) h = feat @ W + b
    gemm_kernel<<<(n_nodes + 63) / 64, 256>>>(feat, W, bias, h, n_nodes);

    // 2) bin edges by dst (counting sort -> CSR + packed pairs)
    zero_cnt_kernel<<<(n_nodes + 255) / 256, 256>>>(n_nodes);
    hist_kernel<<<(n_edges + 255) / 256, 256>>>(dst, n_edges);
    scan1_kernel<<<(n_nodes + 255) / 256, 256>>>(n_nodes);
    scan2_kernel<<<1, 512>>>();
    scan3_kernel<<<(n_nodes + 255) / 256, 256>>>(n_nodes, n_edges);
    perm_kernel<<<(n_edges + 255) / 256, 256>>>(src, dst, att, n_edges);

    // 3) atomic-free accumulation, warp per node
    long long work = (long long)n_nodes * 32;
    accum_kernel<<<(int)((work + 255) / 256), 256>>>(h, out, n_nodes);
}

// round 5
// speedup vs baseline: 2.1182x; 1.0549x over previous
#include <cuda_runtime.h>
#include <cuda_fp16.h>
#include <cstdint>

#define IN_FEAT   64
#define OUT_FEAT  64
#define MAX_NODES 100000
#define MAX_EDGES 1600000
#define NB_SCAN   ((MAX_NODES + 255) / 256)   // 391

// Scratch (__device__ globals: allocation-free)
__device__ __half2 g_h16[MAX_NODES * 32];         // h in fp16 (12.8 MB)
__device__ int   g_cnt[MAX_NODES];                // histogram
__device__ int   g_off[MAX_NODES + 1];            // CSR offsets
__device__ int   g_cur[MAX_NODES];                // scatter cursors
__device__ int   g_bsum[NB_SCAN];                 // scan block sums
__device__ int2  g_pair[MAX_EDGES];               // dst-sorted (src, att)

// ---------------------------------------------------------------------------
// Kernel 1: h = feat @ W + b -> fp16.  128x64 tile/block, 8x4 micro-tile.
// ---------------------------------------------------------------------------
__global__ __launch_bounds__(256) void gemm_kernel(
    const float* __restrict__ feat,
    const float* __restrict__ W,
    const float* __restrict__ bias,
    __half2* __restrict__ h16,
    int n_nodes)
{
    __shared__ float sF[IN_FEAT][132];   // [k][local_row], 128 rows + pad
    __shared__ float sW[IN_FEAT][68];    // [k][col]

    const int tid  = threadIdx.x;
    const int row0 = blockIdx.x * 128;

    // ---- stage W (coalesced) ----
    {
        int k  = tid >> 2;
        int c4 = tid & 3;
        const float4* wsrc = reinterpret_cast<const float4*>(W + k * OUT_FEAT + c4 * 16);
#pragma unroll
        for (int i = 0; i < 4; i++) {
            float4 v = wsrc[i];
            int c = c4 * 16 + i * 4;
            sW[k][c + 0] = v.x; sW[k][c + 1] = v.y;
            sW[k][c + 2] = v.z; sW[k][c + 3] = v.w;
        }
    }
    // ---- stage feat tile transposed: thread loads half a row (32 floats) ----
    {
        int rl   = tid >> 1;             // 0..127
        int half = tid & 1;              // which 32-col half
        int grow = row0 + rl;
        const float* frow = feat + (size_t)grow * IN_FEAT + half * 32;
#pragma unroll
        for (int i = 0; i < 8; i++) {
            float4 v = (grow < n_nodes)
                ? *reinterpret_cast<const float4*>(frow + i * 4)
                : make_float4(0.f, 0.f, 0.f, 0.f);
            int k = half * 32 + i * 4;
            sF[k + 0][rl] = v.x; sF[k + 1][rl] = v.y;
            sF[k + 2][rl] = v.z; sF[k + 3][rl] = v.w;
        }
    }
    __syncthreads();

    const int tx = tid & 15;    // col group (4 cols)
    const int ty = tid >> 4;    // row group (8 rows)

    float acc[8][4];
#pragma unroll
    for (int j = 0; j < 4; j++) {
        float b = __ldg(bias + tx * 4 + j);
#pragma unroll
        for (int i = 0; i < 8; i++) acc[i][j] = b;
    }

#pragma unroll 4
    for (int k = 0; k < IN_FEAT; k++) {
        float4 a0 = *reinterpret_cast<const float4*>(&sF[k][ty * 8]);
        float4 a1 = *reinterpret_cast<const float4*>(&sF[k][ty * 8 + 4]);
        float4 b  = *reinterpret_cast<const float4*>(&sW[k][tx * 4]);
        float af[8] = {a0.x, a0.y, a0.z, a0.w, a1.x, a1.y, a1.z, a1.w};
        float bf[4] = {b.x, b.y, b.z, b.w};
#pragma unroll
        for (int i = 0; i < 8; i++)
#pragma unroll
            for (int j = 0; j < 4; j++)
                acc[i][j] = fmaf(af[i], bf[j], acc[i][j]);
    }

#pragma unroll
    for (int i = 0; i < 8; i++) {
        int grow = row0 + ty * 8 + i;
        if (grow < n_nodes) {
            __half2 p0 = __floats2half2_rn(acc[i][0], acc[i][1]);
            __half2 p1 = __floats2half2_rn(acc[i][2], acc[i][3]);
            uint2 u;
            u.x = *reinterpret_cast<uint32_t*>(&p0);
            u.y = *reinterpret_cast<uint32_t*>(&p1);
            *reinterpret_cast<uint2*>(h16 + (size_t)grow * 32 + tx * 2) = u;
        }
    }
}

// ---------------------------------------------------------------------------
// Binning: counting sort of edges by dst
// ---------------------------------------------------------------------------
__global__ void hist_kernel(const int* __restrict__ dst, int n_edges)
{
    int e = blockIdx.x * blockDim.x + threadIdx.x;
    if (e < n_edges) atomicAdd(&g_cnt[dst[e]], 1);
}

// scan1: per-block inclusive scan (shuffle-based)
__global__ __launch_bounds__(256) void scan1_kernel(int n)
{
    __shared__ int wsum[8];
    int i    = blockIdx.x * 256 + threadIdx.x;
    int lane = threadIdx.x & 31;
    int wid  = threadIdx.x >> 5;
    int v    = (i < n) ? g_cnt[i] : 0;
    int x = v;
#pragma unroll
    for (int off = 1; off < 32; off <<= 1) {
        int t = __shfl_up_sync(0xffffffff, x, off);
        if (lane >= off) x += t;
    }
    if (lane == 31) wsum[wid] = x;
    __syncthreads();
    if (wid == 0) {
        int s = (lane < 8) ? wsum[lane] : 0;
#pragma unroll
        for (int off = 1; off < 8; off <<= 1) {
            int t = __shfl_up_sync(0xffffffff, s, off);
            if (lane >= off) s += t;
        }
        if (lane < 8) wsum[lane] = s;
    }
    __syncthreads();
    int incl = x + (wid > 0 ? wsum[wid - 1] : 0);
    if (i < n) g_off[i] = incl;
    if (threadIdx.x == 255) g_bsum[blockIdx.x] = incl;
}

// scan2: single-block exclusive scan of block sums
__global__ __launch_bounds__(512) void scan2_kernel()
{
    __shared__ int s[512];
    int t = threadIdx.x;
    s[t] = (t < NB_SCAN) ? g_bsum[t] : 0;
    __syncthreads();
#pragma unroll
    for (int off = 1; off < 512; off <<= 1) {
        int v = (t >= off) ? s[t - off] : 0;
        __syncthreads();
        s[t] += v;
        __syncthreads();
    }
    if (t < NB_SCAN) g_bsum[t] = (t > 0) ? s[t - 1] : 0;
}

// scan3: global exclusive offsets + cursors
__global__ __launch_bounds__(256) void scan3_kernel(int n, int n_edges)
{
    int i = blockIdx.x * 256 + threadIdx.x;
    if (i < n) {
        int excl = g_off[i] - g_cnt[i] + g_bsum[blockIdx.x];
        g_off[i] = excl;
        g_cur[i] = excl;
    }
    if (i == 0) g_off[n] = n_edges;
}

// perm: place packed (src, att) pairs in dst-sorted order
__global__ void perm_kernel(const int* __restrict__ src,
                            const int* __restrict__ dst,
                            const float* __restrict__ att,
                            int n_edges)
{
    int e = blockIdx.x * blockDim.x + threadIdx.x;
    if (e >= n_edges) return;
    int d = dst[e];
    int p = atomicAdd(&g_cur[d], 1);
    g_pair[p] = make_int2(src[e], __float_as_int(att[e]));
}

// ---------------------------------------------------------------------------
// Accumulate: one warp per dst node; lane owns 2 cols (one half2 = 4B gather).
// fp32 accumulation, atomic-free.
// ---------------------------------------------------------------------------
__global__ __launch_bounds__(256) void accum_kernel(
    const __half2* __restrict__ h16,
    float* __restrict__ out,
    int n_nodes)
{
    int warp = (blockIdx.x * 256 + threadIdx.x) >> 5;
    int lane = threadIdx.x & 31;
    if (warp >= n_nodes) return;

    int j   = g_off[warp];
    int end = g_off[warp + 1];

    float2 acc = make_float2(0.f, 0.f);

    for (; j + 3 < end; j += 4) {
        int2 p0 = __ldg(&g_pair[j]);
        int2 p1 = __ldg(&g_pair[j + 1]);
        int2 p2 = __ldg(&g_pair[j + 2]);
        int2 p3 = __ldg(&g_pair[j + 3]);
        float2 v0 = __half22float2(__ldg(h16 + (size_t)p0.x * 32 + lane));
        float2 v1 = __half22float2(__ldg(h16 + (size_t)p1.x * 32 + lane));
        float2 v2 = __half22float2(__ldg(h16 + (size_t)p2.x * 32 + lane));
        float2 v3 = __half22float2(__ldg(h16 + (size_t)p3.x * 32 + lane));
        float a0 = __int_as_float(p0.y), a1 = __int_as_float(p1.y);
        float a2 = __int_as_float(p2.y), a3 = __int_as_float(p3.y);
        acc.x = fmaf(a0, v0.x, acc.x); acc.y = fmaf(a0, v0.y, acc.y);
        acc.x = fmaf(a1, v1.x, acc.x); acc.y = fmaf(a1, v1.y, acc.y);
        acc.x = fmaf(a2, v2.x, acc.x); acc.y = fmaf(a2, v2.y, acc.y);
        acc.x = fmaf(a3, v3.x, acc.x); acc.y = fmaf(a3, v3.y, acc.y);
    }
    for (; j < end; j++) {
        int2 p = __ldg(&g_pair[j]);
        float a = __int_as_float(p.y);
        float2 v = __half22float2(__ldg(h16 + (size_t)p.x * 32 + lane));
        acc.x = fmaf(a, v.x, acc.x);
        acc.y = fmaf(a, v.y, acc.y);
    }

    *reinterpret_cast<float2*>(out + (size_t)warp * OUT_FEAT + lane * 2) = acc;
}

// ---------------------------------------------------------------------------
// Launch
// ---------------------------------------------------------------------------
extern "C" void kernel_launch(void* const* d_in, const int* in_sizes, int n_in,
                              void* d_out, int out_size)
{
    const float* feat = (const float*)d_in[0];
    const float* att  = (const float*)d_in[1];
    const int*   src  = (const int*)  d_in[2];
    const int*   dst  = (const int*)  d_in[3];
    const float* W    = (const float*)d_in[4];
    const float* bias = (const float*)d_in[5];
    float*       out  = (float*)d_out;

    int n_nodes = in_sizes[0] / IN_FEAT;
    int n_edges = in_sizes[2];

    __half2* h16;
    cudaGetSymbolAddress((void**)&h16, g_h16);
    int* cnt;
    cudaGetSymbolAddress((void**)&cnt, g_cnt);

    // 1) h = feat @ W + b  (fp16 output)
    gemm_kernel<<<(n_nodes + 127) / 128, 256>>>(feat, W, bias, h16, n_nodes);

    // 2) bin edges by dst
    cudaMemsetAsync(cnt, 0, (size_t)n_nodes * sizeof(int));
    hist_kernel<<<(n_edges + 255) / 256, 256>>>(dst, n_edges);
    scan1_kernel<<<(n_nodes + 255) / 256, 256>>>(n_nodes);
    scan2_kernel<<<1, 512>>>();
    scan3_kernel<<<(n_nodes + 255) / 256, 256>>>(n_nodes, n_edges);
    perm_kernel<<<(n_edges + 255) / 256, 256>>>(src, dst, att, n_edges);

    // 3) atomic-free accumulation, warp per node
    long long work = (long long)n_nodes * 32;
    accum_kernel<<<(int)((work + 255) / 256), 256>>>(h16, out, n_nodes);
}

// round 6
// speedup vs baseline: 2.2667x; 1.0701x over previous
#include <cuda_runtime.h>
#include <cuda_fp16.h>
#include <cstdint>

#define IN_FEAT   64
#define OUT_FEAT  64
#define MAX_NODES 100000
#define MAX_EDGES 1600000
#define NB_SCAN   ((MAX_NODES + 255) / 256)   // 391

// Scratch (__device__ globals: allocation-free, zero-initialized at load)
__device__ __half2 g_h16[MAX_NODES * 32];         // h in fp16 (12.8 MB)
__device__ int   g_cnt[MAX_NODES];                // histogram (zero-invariant)
__device__ int   g_off[MAX_NODES + 1];            // CSR offsets
__device__ int   g_cur[MAX_NODES];                // scatter cursors
__device__ int   g_bsum[NB_SCAN];                 // scan block sums
__device__ int2  g_pair[MAX_EDGES];               // dst-sorted (src, att)

// ---------------------------------------------------------------------------
// Kernel 1: h = feat @ W + b -> fp16.  128x64 tile/block, 8x4 micro-tile.
// ---------------------------------------------------------------------------
__global__ __launch_bounds__(256) void gemm_kernel(
    const float* __restrict__ feat,
    const float* __restrict__ W,
    const float* __restrict__ bias,
    __half2* __restrict__ h16,
    int n_nodes)
{
    __shared__ float sF[IN_FEAT][132];
    __shared__ float sW[IN_FEAT][68];

    const int tid  = threadIdx.x;
    const int row0 = blockIdx.x * 128;

    {
        int k  = tid >> 2;
        int c4 = tid & 3;
        const float4* wsrc = reinterpret_cast<const float4*>(W + k * OUT_FEAT + c4 * 16);
#pragma unroll
        for (int i = 0; i < 4; i++) {
            float4 v = wsrc[i];
            int c = c4 * 16 + i * 4;
            sW[k][c + 0] = v.x; sW[k][c + 1] = v.y;
            sW[k][c + 2] = v.z; sW[k][c + 3] = v.w;
        }
    }
    {
        int rl   = tid >> 1;
        int half = tid & 1;
        int grow = row0 + rl;
        const float* frow = feat + (size_t)grow * IN_FEAT + half * 32;
#pragma unroll
        for (int i = 0; i < 8; i++) {
            float4 v = (grow < n_nodes)
                ? *reinterpret_cast<const float4*>(frow + i * 4)
                : make_float4(0.f, 0.f, 0.f, 0.f);
            int k = half * 32 + i * 4;
            sF[k + 0][rl] = v.x; sF[k + 1][rl] = v.y;
            sF[k + 2][rl] = v.z; sF[k + 3][rl] = v.w;
        }
    }
    __syncthreads();

    const int tx = tid & 15;
    const int ty = tid >> 4;

    float acc[8][4];
#pragma unroll
    for (int j = 0; j < 4; j++) {
        float b = __ldg(bias + tx * 4 + j);
#pragma unroll
        for (int i = 0; i < 8; i++) acc[i][j] = b;
    }

#pragma unroll 4
    for (int k = 0; k < IN_FEAT; k++) {
        float4 a0 = *reinterpret_cast<const float4*>(&sF[k][ty * 8]);
        float4 a1 = *reinterpret_cast<const float4*>(&sF[k][ty * 8 + 4]);
        float4 b  = *reinterpret_cast<const float4*>(&sW[k][tx * 4]);
        float af[8] = {a0.x, a0.y, a0.z, a0.w, a1.x, a1.y, a1.z, a1.w};
        float bf[4] = {b.x, b.y, b.z, b.w};
#pragma unroll
        for (int i = 0; i < 8; i++)
#pragma unroll
            for (int j = 0; j < 4; j++)
                acc[i][j] = fmaf(af[i], bf[j], acc[i][j]);
    }

#pragma unroll
    for (int i = 0; i < 8; i++) {
        int grow = row0 + ty * 8 + i;
        if (grow < n_nodes) {
            __half2 p0 = __floats2half2_rn(acc[i][0], acc[i][1]);
            __half2 p1 = __floats2half2_rn(acc[i][2], acc[i][3]);
            uint2 u;
            u.x = *reinterpret_cast<uint32_t*>(&p0);
            u.y = *reinterpret_cast<uint32_t*>(&p1);
            *reinterpret_cast<uint2*>(h16 + (size_t)grow * 32 + tx * 2) = u;
        }
    }
}

// ---------------------------------------------------------------------------
// hist: count edges per dst (g_cnt is zero on entry — invariant)
// ---------------------------------------------------------------------------
__global__ void hist_kernel(const int* __restrict__ dst, int n_edges)
{
    int e = blockIdx.x * blockDim.x + threadIdx.x;
    if (e < n_edges) atomicAdd(&g_cnt[dst[e]], 1);
}

// ---------------------------------------------------------------------------
// scan1: per-block EXCLUSIVE scan of g_cnt -> g_off (block-local),
//        block totals -> g_bsum, and re-zero g_cnt (restores invariant).
// ---------------------------------------------------------------------------
__global__ __launch_bounds__(256) void scan1_kernel(int n)
{
    __shared__ int wsum[8];
    int i    = blockIdx.x * 256 + threadIdx.x;
    int lane = threadIdx.x & 31;
    int wid  = threadIdx.x >> 5;
    int v    = (i < n) ? g_cnt[i] : 0;
    if (i < n) g_cnt[i] = 0;              // restore zero-invariant for next replay

    int x = v;
#pragma unroll
    for (int off = 1; off < 32; off <<= 1) {
        int t = __shfl_up_sync(0xffffffff, x, off);
        if (lane >= off) x += t;
    }
    if (lane == 31) wsum[wid] = x;
    __syncthreads();
    if (wid == 0) {
        int s = (lane < 8) ? wsum[lane] : 0;
#pragma unroll
        for (int off = 1; off < 8; off <<= 1) {
            int t = __shfl_up_sync(0xffffffff, s, off);
            if (lane >= off) s += t;
        }
        if (lane < 8) wsum[lane] = s;
    }
    __syncthreads();
    int incl = x + (wid > 0 ? wsum[wid - 1] : 0);
    if (i < n) g_off[i] = incl - v;       // block-local exclusive
    if (threadIdx.x == 255) g_bsum[blockIdx.x] = incl;
}

// ---------------------------------------------------------------------------
// scan2b: each block redundantly reduces g_bsum[0..blockIdx) for its prefix,
//         applies global offset, initializes cursors, writes g_off[n].
// ---------------------------------------------------------------------------
__global__ __launch_bounds__(256) void scan2b_kernel(int n, int n_edges)
{
    __shared__ int wred[8];
    int tid  = threadIdx.x;
    int lane = tid & 31;
    int wid  = tid >> 5;
    int b    = blockIdx.x;

    int local = 0;
    for (int t = tid; t < b; t += 256) local += g_bsum[t];
#pragma unroll
    for (int off = 16; off > 0; off >>= 1)
        local += __shfl_down_sync(0xffffffff, local, off);
    if (lane == 0) wred[wid] = local;
    __syncthreads();
    if (wid == 0) {
        int s = (lane < 8) ? wred[lane] : 0;
#pragma unroll
        for (int off = 4; off > 0; off >>= 1)
            s += __shfl_down_sync(0xffffffff, s, off);
        if (lane == 0) wred[0] = s;
    }
    __syncthreads();
    int prefix = wred[0];

    int i = b * 256 + tid;
    if (i < n) {
        int excl = g_off[i] + prefix;
        g_off[i] = excl;
        g_cur[i] = excl;
    }
    if (b == 0 && tid == 0) g_off[n] = n_edges;
}

// ---------------------------------------------------------------------------
// perm: place packed (src, att) pairs in dst-sorted order
// ---------------------------------------------------------------------------
__global__ void perm_kernel(const int* __restrict__ src,
                            const int* __restrict__ dst,
                            const float* __restrict__ att,
                            int n_edges)
{
    int e = blockIdx.x * blockDim.x + threadIdx.x;
    if (e >= n_edges) return;
    int d = dst[e];
    int p = atomicAdd(&g_cur[d], 1);
    g_pair[p] = make_int2(src[e], __float_as_int(att[e]));
}

// ---------------------------------------------------------------------------
// accum: one warp per dst node; lane owns 2 cols; fp32 accumulation.
// ---------------------------------------------------------------------------
__global__ __launch_bounds__(256) void accum_kernel(
    const __half2* __restrict__ h16,
    float* __restrict__ out,
    int n_nodes)
{
    int warp = (blockIdx.x * 256 + threadIdx.x) >> 5;
    int lane = threadIdx.x & 31;
    if (warp >= n_nodes) return;

    int j   = g_off[warp];
    int end = g_off[warp + 1];

    float2 acc = make_float2(0.f, 0.f);

    for (; j + 3 < end; j += 4) {
        int2 p0 = __ldg(&g_pair[j]);
        int2 p1 = __ldg(&g_pair[j + 1]);
        int2 p2 = __ldg(&g_pair[j + 2]);
        int2 p3 = __ldg(&g_pair[j + 3]);
        float2 v0 = __half22float2(__ldg(h16 + (size_t)p0.x * 32 + lane));
        float2 v1 = __half22float2(__ldg(h16 + (size_t)p1.x * 32 + lane));
        float2 v2 = __half22float2(__ldg(h16 + (size_t)p2.x * 32 + lane));
        float2 v3 = __half22float2(__ldg(h16 + (size_t)p3.x * 32 + lane));
        float a0 = __int_as_float(p0.y), a1 = __int_as_float(p1.y);
        float a2 = __int_as_float(p2.y), a3 = __int_as_float(p3.y);
        acc.x = fmaf(a0, v0.x, acc.x); acc.y = fmaf(a0, v0.y, acc.y);
        acc.x = fmaf(a1, v1.x, acc.x); acc.y = fmaf(a1, v1.y, acc.y);
        acc.x = fmaf(a2, v2.x, acc.x); acc.y = fmaf(a2, v2.y, acc.y);
        acc.x = fmaf(a3, v3.x, acc.x); acc.y = fmaf(a3, v3.y, acc.y);
    }
    for (; j < end; j++) {
        int2 p = __ldg(&g_pair[j]);
        float a = __int_as_float(p.y);
        float2 v = __half22float2(__ldg(h16 + (size_t)p.x * 32 + lane));
        acc.x = fmaf(a, v.x, acc.x);
        acc.y = fmaf(a, v.y, acc.y);
    }

    *reinterpret_cast<float2*>(out + (size_t)warp * OUT_FEAT + lane * 2) = acc;
}

// ---------------------------------------------------------------------------
// Launch: GEMM forked onto a side stream, concurrent with binning chain.
// Stream/event handles are host-side objects (no device memory); created per
// call and intentionally not destroyed (destroying a capture-participating
// stream would invalidate the capture; kernel_launch runs only 2-3 times).
// ---------------------------------------------------------------------------
extern "C" void kernel_launch(void* const* d_in, const int* in_sizes, int n_in,
                              void* d_out, int out_size)
{
    const float* feat = (const float*)d_in[0];
    const float* att  = (const float*)d_in[1];
    const int*   src  = (const int*)  d_in[2];
    const int*   dst  = (const int*)  d_in[3];
    const float* W    = (const float*)d_in[4];
    const float* bias = (const float*)d_in[5];
    float*       out  = (float*)d_out;

    int n_nodes = in_sizes[0] / IN_FEAT;
    int n_edges = in_sizes[2];

    __half2* h16;
    cudaGetSymbolAddress((void**)&h16, g_h16);

    cudaStream_t side;
    cudaStreamCreateWithFlags(&side, cudaStreamNonBlocking);
    cudaEvent_t evFork, evJoin;
    cudaEventCreateWithFlags(&evFork, cudaEventDisableTiming);
    cudaEventCreateWithFlags(&evJoin, cudaEventDisableTiming);

    // fork: gemm on side stream
    cudaEventRecord(evFork, 0);
    cudaStreamWaitEvent(side, evFork, 0);
    gemm_kernel<<<(n_nodes + 127) / 128, 256, 0, side>>>(feat, W, bias, h16, n_nodes);
    cudaEventRecord(evJoin, side);

    // binning chain on main stream (independent of gemm)
    hist_kernel<<<(n_edges + 255) / 256, 256>>>(dst, n_edges);
    scan1_kernel<<<(n_nodes + 255) / 256, 256>>>(n_nodes);
    scan2b_kernel<<<(n_nodes + 255) / 256, 256>>>(n_nodes, n_edges);
    perm_kernel<<<(n_edges + 255) / 256, 256>>>(src, dst, att, n_edges);

    // join, then accumulate
    cudaStreamWaitEvent(0, evJoin, 0);
    long long work = (long long)n_nodes * 32;
    accum_kernel<<<(int)((work + 255) / 256), 256>>>(h16, out, n_nodes);
}